// round 16
// baseline (speedup 1.0000x reference)
#include <cuda_runtime.h>
#include <cstdint>

// Problem constants
#define Bc 64
#define Sc 2048
#define Dc 512
#define Uc 512
#define TSR 64     // rows per score block
#define KT  16     // K tile
#define NCH 16     // context S-chunks per batch

// Scratch (no allocations allowed)
__device__ float g_qp[Bc * Uc];        // q_proj + b1 + b2
__device__ float g_scores[Bc * Sc];    // raw scores
__device__ float g_max[Bc];
__device__ float g_rsum[Bc];
__device__ float g_part[Bc * NCH * Dc];

// Dynamic smem layout for score_kernel (byte offsets)
#define OFF_W2D 0                       // [KT][Uc] float2{w,w} = 64 KB
#define OFF_VS  65536                   // [TSR/2][KT] u64 row-pairs = 4 KB
#define OFF_RED 69632                   // [TSR][9] floats = 2304 B
#define SMEM_DYN 72192

// ---------------------------------------------------------------------------
// Kernel A: q_proj[b][u] = query[b]@W1[:,u] + b1[u] + b2[u]
// ---------------------------------------------------------------------------
__global__ void qproj_kernel(const float* __restrict__ query,
                             const float* __restrict__ W1,
                             const float* __restrict__ b1,
                             const float* __restrict__ b2) {
    __shared__ float q[Dc];
    const int b = blockIdx.x, t = threadIdx.x;
    q[t] = query[b * Dc + t];
    __syncthreads();
    float acc = b1[t] + b2[t];
#pragma unroll 8
    for (int d = 0; d < Dc; d++)
        acc = fmaf(q[d], W1[d * Uc + t], acc);
    g_qp[b * Uc + t] = acc;
}

// ---------------------------------------------------------------------------
// Kernel B: fused  scores[row] = V . tanh(q_proj[b] + values[row]@W2)
// Block: 64 rows x 512 cols, 512 threads.
// Thread t: row-half ch = t>>8 (32 rows), cols {t&255, (t&255)+256}.
// f32x2-packed accumulators: 16 row-pairs x 2 cols.
// W2 tile stored duplicated {w,w} -> single LDS.64 per broadcast multiplier.
// values row-pairs read as LDS.128 (two k's per load).
// ---------------------------------------------------------------------------
__global__ void __launch_bounds__(512, 1)
score_kernel(const float* __restrict__ values,
             const float* __restrict__ W2,
             const float* __restrict__ Vw) {
    extern __shared__ char sm[];
    unsigned long long* W2d = (unsigned long long*)(sm + OFF_W2D);  // [KT][Uc]
    unsigned long long* Vs2 = (unsigned long long*)(sm + OFF_VS);   // [TSR/2][KT]
    float (*red)[9] = (float(*)[9])(sm + OFF_RED);

    const int t = threadIdx.x;
    const int row0 = blockIdx.x * TSR;   // global row in [0, B*S)
    const int b = row0 >> 11;            // row0 / Sc
    const int ch = t >> 8;               // row half (0/1)
    const int c0 = t & 255;
    const int c1 = c0 + 256;

    unsigned long long acc[16][2];
#pragma unroll
    for (int rp = 0; rp < 16; rp++) { acc[rp][0] = 0ULL; acc[rp][1] = 0ULL; }

    // --- tile loader mappings ---
    // W2 tile: 2048 float4 from global, thread loads 4 (coalesced),
    //          stores duplicated {x,x,y,y}{z,z,w,w} into W2d.
    // values tile: thread reads float2 at (row vr = t>>3, k = (t&7)*2)
    const int vr = t >> 3;
    const int vk = (t & 7) * 2;
    const float* vptr = values + (size_t)(row0 + vr) * Dc + vk;
    float* vsf = (float*)Vs2;
    const int vsi = ((vr >> 1) * KT + vk) * 2 + (vr & 1);  // float index of f2.x slot

    const unsigned long long* vrow = Vs2 + ch * 16 * KT;

    // preload tile 0 into registers
    float4 wreg[4];
    float2 vreg;
    {
        const float4* wsrc = (const float4*)W2;
#pragma unroll
        for (int i = 0; i < 4; i++) wreg[i] = wsrc[t + i * 512];
        vreg = *(const float2*)vptr;
    }

#pragma unroll 1
    for (int kt = 0; kt < Dc / KT; kt++) {
        // stage registers -> shared (W2 duplicated)
#pragma unroll
        for (int i = 0; i < 4; i++) {
            const int j = t + i * 512;
            const int k = j >> 7, u4 = (j & 127) * 4;
            float4 s = wreg[i];
            float4* dst = (float4*)(W2d + (size_t)k * Uc + u4);
            dst[0] = make_float4(s.x, s.x, s.y, s.y);
            dst[1] = make_float4(s.z, s.z, s.w, s.w);
        }
        vsf[vsi]     = vreg.x;
        vsf[vsi + 2] = vreg.y;
        __syncthreads();

        // prefetch next tile into registers (latency hidden under compute)
        if (kt != Dc / KT - 1) {
            const float4* wsrc = (const float4*)(W2 + (size_t)(kt + 1) * KT * Uc);
#pragma unroll
            for (int i = 0; i < 4; i++) wreg[i] = wsrc[t + i * 512];
            vreg = *(const float2*)(vptr + (kt + 1) * KT);
        }

        // compute
#pragma unroll
        for (int kp = 0; kp < 8; kp++) {
            const unsigned long long w00 = W2d[(2 * kp) * Uc + c0];
            const unsigned long long w10 = W2d[(2 * kp + 1) * Uc + c0];
            const unsigned long long w01 = W2d[(2 * kp) * Uc + c1];
            const unsigned long long w11 = W2d[(2 * kp + 1) * Uc + c1];
#pragma unroll
            for (int rp = 0; rp < 16; rp++) {
                const ulonglong2 v = *(const ulonglong2*)(vrow + rp * KT + 2 * kp);
                asm("fma.rn.f32x2 %0, %1, %2, %0;" : "+l"(acc[rp][0]) : "l"(v.x), "l"(w00));
                asm("fma.rn.f32x2 %0, %1, %2, %0;" : "+l"(acc[rp][1]) : "l"(v.x), "l"(w01));
                asm("fma.rn.f32x2 %0, %1, %2, %0;" : "+l"(acc[rp][0]) : "l"(v.y), "l"(w10));
                asm("fma.rn.f32x2 %0, %1, %2, %0;" : "+l"(acc[rp][1]) : "l"(v.y), "l"(w11));
            }
        }
        __syncthreads();
    }

    // --- epilogue: h = tanh(qp + mv), score = sum_u V[u]*h[u] ---
    const float V0 = Vw[c0], V1 = Vw[c1];
    const float qp0 = g_qp[b * Uc + c0], qp1 = g_qp[b * Uc + c1];
    const int lane = t & 31, wrp = t >> 5;  // wrp 0..15; (wrp&7) is slot within half
#pragma unroll
    for (int rp = 0; rp < 16; rp++) {
        float m00, m01, m10, m11;
        asm("mov.b64 {%0, %1}, %2;" : "=f"(m00), "=f"(m01) : "l"(acc[rp][0]));
        asm("mov.b64 {%0, %1}, %2;" : "=f"(m10), "=f"(m11) : "l"(acc[rp][1]));
        float se = V0 * tanhf(qp0 + m00) + V1 * tanhf(qp1 + m10);  // even row
        float so = V0 * tanhf(qp0 + m01) + V1 * tanhf(qp1 + m11);  // odd row
#pragma unroll
        for (int o = 16; o; o >>= 1) {
            se += __shfl_xor_sync(0xffffffffu, se, o);
            so += __shfl_xor_sync(0xffffffffu, so, o);
        }
        if (lane == 0) {
            const int r = ch * 32 + 2 * rp;
            red[r][wrp & 7]     = se;
            red[r + 1][wrp & 7] = so;
        }
    }
    __syncthreads();
    if (t < TSR) {
        float s = 0.f;
#pragma unroll
        for (int w = 0; w < 8; w++) s += red[t][w];
        g_scores[row0 + t] = s;   // bv dropped: softmax shift-invariant
    }
}

// ---------------------------------------------------------------------------
// Kernel C1: per-batch softmax stats (max, 1/sum)
// ---------------------------------------------------------------------------
__global__ void softmax_stats_kernel() {
    __shared__ float sh[Sc];
    __shared__ float r32[32];
    const int b = blockIdx.x, t = threadIdx.x;  // 512 threads
    const int lane = t & 31, wrp = t >> 5;

    float lmax = -1e30f;
#pragma unroll
    for (int i = 0; i < 4; i++) {
        float v = g_scores[b * Sc + t + i * 512];
        sh[t + i * 512] = v;
        lmax = fmaxf(lmax, v);
    }
#pragma unroll
    for (int o = 16; o; o >>= 1) lmax = fmaxf(lmax, __shfl_xor_sync(0xffffffffu, lmax, o));
    if (lane == 0) r32[wrp] = lmax;
    __syncthreads();
    if (t < 32) {
        float v = (t < 16) ? r32[t] : -1e30f;
#pragma unroll
        for (int o = 8; o; o >>= 1) v = fmaxf(v, __shfl_xor_sync(0xffffffffu, v, o));
        if (t == 0) r32[16] = v;
    }
    __syncthreads();
    const float mx = r32[16];

    float ls = 0.f;
#pragma unroll
    for (int i = 0; i < 4; i++) ls += expf(sh[t + i * 512] - mx);
#pragma unroll
    for (int o = 16; o; o >>= 1) ls += __shfl_xor_sync(0xffffffffu, ls, o);
    __syncthreads();
    if (lane == 0) r32[wrp] = ls;
    __syncthreads();
    if (t == 0) {
        float s = 0.f;
        for (int i = 0; i < 16; i++) s += r32[i];
        g_max[b] = mx;
        g_rsum[b] = 1.f / s;
    }
}

// ---------------------------------------------------------------------------
// Kernel C2: partial context over an S-chunk (NCH chunks per batch)
// ---------------------------------------------------------------------------
__global__ void context_partial_kernel(const float* __restrict__ values) {
    __shared__ float ws[Sc / NCH];  // 128 weights
    const int ch = blockIdx.x, b = blockIdx.y, t = threadIdx.x;  // 512 threads
    const float mx = g_max[b], rs = g_rsum[b];
    if (t < Sc / NCH)
        ws[t] = expf(g_scores[b * Sc + ch * (Sc / NCH) + t] - mx) * rs;
    __syncthreads();

    const float* vp = values + (size_t)(b * Sc + ch * (Sc / NCH)) * Dc + t;
    float acc = 0.f;
#pragma unroll 16
    for (int i = 0; i < Sc / NCH; i++)
        acc = fmaf(ws[i], vp[(size_t)i * Dc], acc);
    g_part[(b * NCH + ch) * Dc + t] = acc;
}

// ---------------------------------------------------------------------------
// Kernel C3: reduce NCH partials -> context output [B, D]
// ---------------------------------------------------------------------------
__global__ void context_reduce_kernel(float* __restrict__ out) {
    const int b = blockIdx.x, t = threadIdx.x;
    float s = 0.f;
#pragma unroll
    for (int ch = 0; ch < NCH; ch++)
        s += g_part[(b * NCH + ch) * Dc + t];
    out[b * Dc + t] = s;
}

// ---------------------------------------------------------------------------
extern "C" void kernel_launch(void* const* d_in, const int* in_sizes, int n_in,
                              void* d_out, int out_size) {
    (void)in_sizes; (void)n_in; (void)out_size;
    const float* query  = (const float*)d_in[0];
    const float* values = (const float*)d_in[1];
    const float* W1     = (const float*)d_in[2];
    const float* b1     = (const float*)d_in[3];
    const float* W2     = (const float*)d_in[4];
    const float* b2     = (const float*)d_in[5];
    const float* Vw     = (const float*)d_in[6];
    // d_in[7] = bv: softmax over S is invariant to a constant shift -> unused
    float* out = (float*)d_out;

    cudaFuncSetAttribute(score_kernel, cudaFuncAttributeMaxDynamicSharedMemorySize, SMEM_DYN);

    qproj_kernel<<<Bc, Uc>>>(query, W1, b1, b2);
    score_kernel<<<(Bc * Sc) / TSR, 512, SMEM_DYN>>>(values, W2, Vw);
    softmax_stats_kernel<<<Bc, 512>>>();
    context_partial_kernel<<<dim3(NCH, Bc), 512>>>(values);
    context_reduce_kernel<<<Bc, Dc>>>(out);
}

// round 17
// speedup vs baseline: 2.7525x; 2.7525x over previous
#include <cuda_runtime.h>
#include <cuda_bf16.h>
#include <cstdint>

// Problem constants
#define Bc 64
#define Sc 2048
#define Dc 512
#define Uc 512
#define BS (Bc * Sc)
#define NCH 16

// Score kernel tiling
#define MT 64        // rows per block
#define NH 256       // cols per block (one half of U)
#define KC 32        // K per chunk
#define NKC (Dc / KC)

// SMEM pitches (bank-conflict-free for ldmatrix)
#define PA 80        // A row pitch bytes (32 k bf16 = 64B + 16 pad)
#define PB 528       // B row pitch bytes (256 n bf16 = 512B + 16 pad)
#define A_SZ (MT * PA)            // 5120
#define B_SZ (KC * PB)            // 16896
#define BUF_SZ (2 * A_SZ + 2 * B_SZ)   // Ahi | Alo | Bhi | Blo = 44032
#define OFF_BHI (2 * A_SZ)
#define OFF_BLO (2 * A_SZ + B_SZ)
#define OFF_RED (2 * BUF_SZ)
#define SMEM_DYN (OFF_RED + MT * 4 * 4)

// Scratch (no allocations allowed)
__device__ float g_qp[Bc * Uc];
__device__ float g_scp[2 * BS];     // per-U-half score partials
__device__ float g_scores[BS];
__device__ float g_max[Bc];
__device__ float g_rsum[Bc];
__device__ float g_part[Bc * NCH * Dc];
__device__ __nv_bfloat16 g_W2hi[Dc * Uc];   // [d][u], hi part
__device__ __nv_bfloat16 g_W2lo[Dc * Uc];   // [d][u], lo part

// ---------------------------------------------------------------------------
// helpers
// ---------------------------------------------------------------------------
__device__ __forceinline__ uint32_t smem_u32(const void* p) {
    uint32_t a;
    asm("{ .reg .u64 t; cvta.to.shared.u64 t, %1; cvt.u32.u64 %0, t; }" : "=r"(a) : "l"(p));
    return a;
}
__device__ __forceinline__ void ldm_x4(uint32_t* r, uint32_t addr) {
    asm volatile("ldmatrix.sync.aligned.m8n8.x4.shared.b16 {%0,%1,%2,%3}, [%4];"
                 : "=r"(r[0]), "=r"(r[1]), "=r"(r[2]), "=r"(r[3]) : "r"(addr));
}
__device__ __forceinline__ void ldm_x4_t(uint32_t* r, uint32_t addr) {
    asm volatile("ldmatrix.sync.aligned.m8n8.x4.trans.shared.b16 {%0,%1,%2,%3}, [%4];"
                 : "=r"(r[0]), "=r"(r[1]), "=r"(r[2]), "=r"(r[3]) : "r"(addr));
}
__device__ __forceinline__ void mma16816(float* d, const uint32_t* a, const uint32_t* b) {
    asm volatile("mma.sync.aligned.m16n8k16.row.col.f32.bf16.bf16.f32 "
                 "{%0,%1,%2,%3}, {%4,%5,%6,%7}, {%8,%9}, {%0,%1,%2,%3};"
                 : "+f"(d[0]), "+f"(d[1]), "+f"(d[2]), "+f"(d[3])
                 : "r"(a[0]), "r"(a[1]), "r"(a[2]), "r"(a[3]), "r"(b[0]), "r"(b[1]));
}
__device__ __forceinline__ uint32_t pk(__nv_bfloat16 a, __nv_bfloat16 b) {
    return (uint32_t)__bfloat16_as_ushort(a) | ((uint32_t)__bfloat16_as_ushort(b) << 16);
}
__device__ __forceinline__ void cvt4(float4 f, uint2& H, uint2& L) {
    __nv_bfloat16 h0 = __float2bfloat16(f.x), h1 = __float2bfloat16(f.y);
    __nv_bfloat16 h2 = __float2bfloat16(f.z), h3 = __float2bfloat16(f.w);
    H.x = pk(h0, h1); H.y = pk(h2, h3);
    __nv_bfloat16 l0 = __float2bfloat16(f.x - __bfloat162float(h0));
    __nv_bfloat16 l1 = __float2bfloat16(f.y - __bfloat162float(h1));
    __nv_bfloat16 l2 = __float2bfloat16(f.z - __bfloat162float(h2));
    __nv_bfloat16 l3 = __float2bfloat16(f.w - __bfloat162float(h3));
    L.x = pk(l0, l1); L.y = pk(l2, l3);
}
// fast tanh: 1 - 2/(e^{2x}+1), err ~1e-6
__device__ __forceinline__ float tanh_fast(float x) {
    float e = __expf(2.0f * x);
    return 1.0f - __fdividef(2.0f, e + 1.0f);
}

// ---------------------------------------------------------------------------
// Prep: W2 [d][u] fp32 -> bf16 hi/lo, same layout
// ---------------------------------------------------------------------------
__global__ void prep_w2_kernel(const float* __restrict__ W2) {
    const int d = blockIdx.x, u = threadIdx.x;
    float w = W2[d * Uc + u];
    __nv_bfloat16 h = __float2bfloat16(w);
    g_W2hi[d * Uc + u] = h;
    g_W2lo[d * Uc + u] = __float2bfloat16(w - __bfloat162float(h));
}

// ---------------------------------------------------------------------------
// Kernel A: q_proj[b][u] = query[b]@W1[:,u] + b1[u] + b2[u]
// ---------------------------------------------------------------------------
__global__ void qproj_kernel(const float* __restrict__ query,
                             const float* __restrict__ W1,
                             const float* __restrict__ b1,
                             const float* __restrict__ b2) {
    __shared__ float q[Dc];
    const int b = blockIdx.x, t = threadIdx.x;
    q[t] = query[b * Dc + t];
    __syncthreads();
    float acc = b1[t] + b2[t];
#pragma unroll 8
    for (int d = 0; d < Dc; d++)
        acc = fmaf(q[d], W1[d * Uc + t], acc);
    g_qp[b * Uc + t] = acc;
}

// ---------------------------------------------------------------------------
// Kernel B: HMMA (mma.sync bf16, 3-term split) score GEMM + fused epilogue.
// Block: 64 rows x 256 cols (U-half = blockIdx.y). 256 threads = 8 warps.
// Warp grid 2(M) x 4(N); warp tile 32x64; mma m16n8k16; fp32 accum.
// ---------------------------------------------------------------------------
__global__ void __launch_bounds__(256, 1)
score_kernel(const float* __restrict__ values, const float* __restrict__ Vw) {
    extern __shared__ char sm[];
    const uint32_t sb = smem_u32(sm);

    const int t = threadIdx.x;
    const int w = t >> 5, l = t & 31;
    const int g = l >> 2, tq = l & 3;
    const int wm = w & 1, wn = w >> 1;
    const int row0 = blockIdx.x * MT;
    const int nh = blockIdx.y;
    const int b = row0 >> 11;

    float acc[2][8][4];
#pragma unroll
    for (int mt = 0; mt < 2; mt++)
#pragma unroll
        for (int nt = 0; nt < 8; nt++)
#pragma unroll
            for (int r = 0; r < 4; r++) acc[mt][nt][r] = 0.f;

    // staging registers
    uint4 wh4[4], wl4[4];
    float4 v4[2];

    auto ldg_chunk = [&](int kt) {
#pragma unroll
        for (int i = 0; i < 4; i++) {
            int idx = t + i * 256, r = idx >> 5, c4 = idx & 31;
            size_t go = (size_t)(kt * KC + r) * Uc + nh * NH + c4 * 8;
            wh4[i] = *(const uint4*)(g_W2hi + go);
            wl4[i] = *(const uint4*)(g_W2lo + go);
        }
#pragma unroll
        for (int i = 0; i < 2; i++) {
            int idx = t + i * 256, r = idx >> 3, c4 = idx & 7;
            v4[i] = *(const float4*)(values + (size_t)(row0 + r) * Dc + kt * KC + c4 * 4);
        }
    };

    auto sts_chunk = [&](int p) {
        char* bp = sm + p * BUF_SZ;
#pragma unroll
        for (int i = 0; i < 4; i++) {
            int idx = t + i * 256, r = idx >> 5, c4 = idx & 31;
            *(uint4*)(bp + OFF_BHI + r * PB + c4 * 16) = wh4[i];
            *(uint4*)(bp + OFF_BLO + r * PB + c4 * 16) = wl4[i];
        }
#pragma unroll
        for (int i = 0; i < 2; i++) {
            int idx = t + i * 256, r = idx >> 3, c4 = idx & 7;
            uint2 H, L;
            cvt4(v4[i], H, L);
            *(uint2*)(bp + r * PA + c4 * 8) = H;          // Ahi
            *(uint2*)(bp + A_SZ + r * PA + c4 * 8) = L;   // Alo
        }
    };

    // ldmatrix per-thread address offsets (within a buffer)
    const uint32_t aoff = (uint32_t)(wm * 32 + (l & 15)) * PA + ((uint32_t)(l >> 4)) * 16;
    const uint32_t boff = OFF_BHI + (uint32_t)(l & 15) * PB + (uint32_t)wn * 128
                        + ((uint32_t)(l >> 4)) * 16;

    auto compute = [&](int p) {
        const uint32_t bufb = sb + p * BUF_SZ;
        const uint32_t ab = bufb + aoff;
        const uint32_t bb = bufb + boff;
#pragma unroll
        for (int ks = 0; ks < 2; ks++) {
            uint32_t ah[2][4], al[2][4];
#pragma unroll
            for (int mt = 0; mt < 2; mt++) {
                ldm_x4(ah[mt], ab + mt * 16 * PA + ks * 32);
                ldm_x4(al[mt], ab + A_SZ + mt * 16 * PA + ks * 32);
            }
#pragma unroll
            for (int np = 0; np < 4; np++) {
                uint32_t bh[4], bl[4];
                ldm_x4_t(bh, bb + ks * 16 * PB + np * 32);
                ldm_x4_t(bl, bb + B_SZ + ks * 16 * PB + np * 32);
#pragma unroll
                for (int mt = 0; mt < 2; mt++) {
#pragma unroll
                    for (int n2 = 0; n2 < 2; n2++) {
                        float* d = acc[mt][np * 2 + n2];
                        mma16816(d, ah[mt], bh + n2 * 2);   // hi*hi
                        mma16816(d, ah[mt], bl + n2 * 2);   // hi*lo
                        mma16816(d, al[mt], bh + n2 * 2);   // lo*hi
                    }
                }
            }
        }
    };

    // pipeline: buf[p] holds chunk kt; regs hold chunk kt+1
    ldg_chunk(0);
    sts_chunk(0);
    ldg_chunk(1);
    __syncthreads();
    int p = 0;
#pragma unroll 1
    for (int kt = 0; kt < NKC; kt++) {
        if (kt < NKC - 1) {
            sts_chunk(p ^ 1);
            if (kt < NKC - 2) ldg_chunk(kt + 2);
        }
        compute(p);
        __syncthreads();
        p ^= 1;
    }

    // --- epilogue: score partial = sum_u V[u]*tanh(qp[u] + mv[u]) over this U-half ---
    float q16[16], v16[16];
    const int ubase = nh * NH + wn * 64 + tq * 2;
#pragma unroll
    for (int ci = 0; ci < 16; ci++) {
        int u = ubase + (ci >> 1) * 8 + (ci & 1);
        q16[ci] = __ldg(&g_qp[b * Uc + u]);
        v16[ci] = __ldg(&Vw[u]);
    }
    float rs[4] = {0.f, 0.f, 0.f, 0.f};
#pragma unroll
    for (int mt = 0; mt < 2; mt++)
#pragma unroll
        for (int nt = 0; nt < 8; nt++)
#pragma unroll
            for (int r = 0; r < 4; r++) {
                int ci = nt * 2 + (r & 1);
                rs[mt * 2 + (r >> 1)] += v16[ci] * tanh_fast(q16[ci] + acc[mt][nt][r]);
            }
#pragma unroll
    for (int j = 0; j < 4; j++) {
        rs[j] += __shfl_xor_sync(0xffffffffu, rs[j], 1);
        rs[j] += __shfl_xor_sync(0xffffffffu, rs[j], 2);
    }
    float* red = (float*)(sm + OFF_RED);
    if (tq == 0) {
#pragma unroll
        for (int j = 0; j < 4; j++) {
            int row = wm * 32 + (j & 1) * 8 + (j >> 1) * 16 + g;
            red[row * 4 + wn] = rs[j];
        }
    }
    __syncthreads();
    if (t < MT) {
        float s = red[t * 4] + red[t * 4 + 1] + red[t * 4 + 2] + red[t * 4 + 3];
        g_scp[nh * BS + row0 + t] = s;   // bv dropped: softmax shift-invariant
    }
}

// ---------------------------------------------------------------------------
// Kernel C1: combine U-halves, per-batch softmax stats (max, 1/sum)
// ---------------------------------------------------------------------------
__global__ void softmax_stats_kernel() {
    __shared__ float sh[Sc];
    __shared__ float r32[32];
    const int b = blockIdx.x, t = threadIdx.x;  // 512 threads
    const int lane = t & 31, wrp = t >> 5;

    float lmax = -1e30f;
#pragma unroll
    for (int i = 0; i < 4; i++) {
        int idx = b * Sc + t + i * 512;
        float v = g_scp[idx] + g_scp[BS + idx];
        g_scores[idx] = v;
        sh[t + i * 512] = v;
        lmax = fmaxf(lmax, v);
    }
#pragma unroll
    for (int o = 16; o; o >>= 1) lmax = fmaxf(lmax, __shfl_xor_sync(0xffffffffu, lmax, o));
    if (lane == 0) r32[wrp] = lmax;
    __syncthreads();
    if (t < 32) {
        float v = (t < 16) ? r32[t] : -1e30f;
#pragma unroll
        for (int o = 8; o; o >>= 1) v = fmaxf(v, __shfl_xor_sync(0xffffffffu, v, o));
        if (t == 0) r32[16] = v;
    }
    __syncthreads();
    const float mx = r32[16];

    float ls = 0.f;
#pragma unroll
    for (int i = 0; i < 4; i++) ls += expf(sh[t + i * 512] - mx);
#pragma unroll
    for (int o = 16; o; o >>= 1) ls += __shfl_xor_sync(0xffffffffu, ls, o);
    __syncthreads();
    if (lane == 0) r32[wrp] = ls;
    __syncthreads();
    if (t == 0) {
        float s = 0.f;
        for (int i = 0; i < 16; i++) s += r32[i];
        g_max[b] = mx;
        g_rsum[b] = 1.f / s;
    }
}

// ---------------------------------------------------------------------------
// Kernel C2: partial context over an S-chunk (NCH chunks per batch)
// ---------------------------------------------------------------------------
__global__ void context_partial_kernel(const float* __restrict__ values) {
    __shared__ float ws[Sc / NCH];
    const int ch = blockIdx.x, b = blockIdx.y, t = threadIdx.x;  // 512 threads
    const float mx = g_max[b], rs = g_rsum[b];
    if (t < Sc / NCH)
        ws[t] = expf(g_scores[b * Sc + ch * (Sc / NCH) + t] - mx) * rs;
    __syncthreads();

    const float* vp = values + (size_t)(b * Sc + ch * (Sc / NCH)) * Dc + t;
    float acc = 0.f;
#pragma unroll 16
    for (int i = 0; i < Sc / NCH; i++)
        acc = fmaf(ws[i], vp[(size_t)i * Dc], acc);
    g_part[(b * NCH + ch) * Dc + t] = acc;
}

// ---------------------------------------------------------------------------
// Kernel C3: reduce NCH partials -> context output [B, D]
// ---------------------------------------------------------------------------
__global__ void context_reduce_kernel(float* __restrict__ out) {
    const int b = blockIdx.x, t = threadIdx.x;
    float s = 0.f;
#pragma unroll
    for (int ch = 0; ch < NCH; ch++)
        s += g_part[(b * NCH + ch) * Dc + t];
    out[b * Dc + t] = s;
}

// ---------------------------------------------------------------------------
extern "C" void kernel_launch(void* const* d_in, const int* in_sizes, int n_in,
                              void* d_out, int out_size) {
    (void)in_sizes; (void)n_in; (void)out_size;
    const float* query  = (const float*)d_in[0];
    const float* values = (const float*)d_in[1];
    const float* W1     = (const float*)d_in[2];
    const float* b1     = (const float*)d_in[3];
    const float* W2     = (const float*)d_in[4];
    const float* b2     = (const float*)d_in[5];
    const float* Vw     = (const float*)d_in[6];
    // d_in[7] = bv: softmax over S is invariant to a constant shift -> unused
    float* out = (float*)d_out;

    cudaFuncSetAttribute(score_kernel, cudaFuncAttributeMaxDynamicSharedMemorySize, SMEM_DYN);

    prep_w2_kernel<<<Dc, Uc>>>(W2);
    qproj_kernel<<<Bc, Uc>>>(query, W1, b1, b2);
    score_kernel<<<dim3(BS / MT, 2), 256, SMEM_DYN>>>(values, Vw);
    softmax_stats_kernel<<<Bc, 512>>>();
    context_partial_kernel<<<dim3(NCH, Bc), 512>>>(values);
    context_reduce_kernel<<<Bc, Dc>>>(out);
}